// round 14
// baseline (speedup 1.0000x reference)
#include <cuda_runtime.h>
#include <cuda_fp16.h>
#include <math.h>
#include <stdint.h>

#define TOK   (4*4096)
#define DMODEL 512
#define QKVN  1536
#define MLPD   2048
#define NH     8
#define DH     64
#define BS     128
#define NBLK   32
#define GRID_P3 444       // 148 SMs x 3 CTAs

// ================= scratch =================
__device__ __half g_xin[TOK*DMODEL];
__device__ __half g_qkv[TOK*QKVN];
__device__ __half g_ctx[TOK*DMODEL];
__device__ float  g_x  [TOK*DMODEL];
__device__ __half g_y  [TOK*DMODEL];
__device__ __half g_h  [TOK*MLPD];
__device__ __half g_wqkv[DMODEL*QKVN];
__device__ __half g_wo  [DMODEL*DMODEL];
__device__ __half g_w1  [DMODEL*MLPD];
__device__ __half g_w2  [MLPD*DMODEL];

// ================= small helpers =================
__device__ __forceinline__ uint32_t smem_cast(const void* p) {
    return (uint32_t)__cvta_generic_to_shared(p);
}
__device__ __forceinline__ void cp16(uint32_t s, const void* g) {
    asm volatile("cp.async.cg.shared.global [%0], [%1], 16;" :: "r"(s), "l"(g));
}
#define CP_COMMIT() asm volatile("cp.async.commit_group;")
#define CP_WAIT(n)  asm volatile("cp.async.wait_group %0;" :: "n"(n))

__device__ __forceinline__ void ldsm4(uint32_t* r, uint32_t a) {
    asm volatile("ldmatrix.sync.aligned.m8n8.x4.shared.b16 {%0,%1,%2,%3}, [%4];"
                 : "=r"(r[0]), "=r"(r[1]), "=r"(r[2]), "=r"(r[3]) : "r"(a));
}
__device__ __forceinline__ void ldsm4t(uint32_t* r, uint32_t a) {
    asm volatile("ldmatrix.sync.aligned.m8n8.x4.trans.shared.b16 {%0,%1,%2,%3}, [%4];"
                 : "=r"(r[0]), "=r"(r[1]), "=r"(r[2]), "=r"(r[3]) : "r"(a));
}
__device__ __forceinline__ void mma16816(float* d, const uint32_t* a, const uint32_t* b) {
    asm volatile("mma.sync.aligned.m16n8k16.row.col.f32.f16.f16.f32 "
                 "{%0,%1,%2,%3},{%4,%5,%6,%7},{%8,%9},{%0,%1,%2,%3};"
                 : "+f"(d[0]), "+f"(d[1]), "+f"(d[2]), "+f"(d[3])
                 : "r"(a[0]), "r"(a[1]), "r"(a[2]), "r"(a[3]), "r"(b[0]), "r"(b[1]));
}

__device__ __forceinline__ float gelu_f(float x) {
    float x3 = x * x * x;
    return 0.5f * x * (1.0f + tanhf(0.7978845608028654f * (x + 0.044715f * x3)));
}

// ================= fused prep: weight conversion + LN1 in ONE launch =================
#define WCONV_ELEMS (4*DMODEL*DMODEL + 2*DMODEL*MLPD)
#define WCONV_BLOCKS (WCONV_ELEMS / 4 / 256)
#define LN1_BLOCKS (TOK / 8)
#define PREP_BLOCKS (WCONV_BLOCKS + LN1_BLOCKS)

__device__ __forceinline__ void ln_row_f16(const float* __restrict__ x,
                                           const float* __restrict__ scale,
                                           const float* __restrict__ bias,
                                           __half* __restrict__ out,
                                           int token, int lane)
{
    const float* row = x + (size_t)token * DMODEL;
    float4 v[4];
    float sum = 0.f;
#pragma unroll
    for (int i = 0; i < 4; i++) {
        v[i] = *(const float4*)&row[lane*4 + i*128];
        sum += v[i].x + v[i].y + v[i].z + v[i].w;
    }
#pragma unroll
    for (int o = 16; o; o >>= 1) sum += __shfl_xor_sync(0xffffffffu, sum, o);
    float mu = sum * (1.0f / DMODEL);
    float var = 0.f;
#pragma unroll
    for (int i = 0; i < 4; i++) {
        float dx = v[i].x - mu, dy = v[i].y - mu, dz = v[i].z - mu, dw = v[i].w - mu;
        var += dx*dx + dy*dy + dz*dz + dw*dw;
    }
#pragma unroll
    for (int o = 16; o; o >>= 1) var += __shfl_xor_sync(0xffffffffu, var, o);
    float rstd = rsqrtf(var * (1.0f / DMODEL) + 1e-6f);

    size_t base = (size_t)token * DMODEL;
#pragma unroll
    for (int i = 0; i < 4; i++) {
        int c = lane*4 + i*128;
        float4 sc = *(const float4*)&scale[c];
        float4 bi = *(const float4*)&bias[c];
        float o0 = (v[i].x - mu) * rstd * sc.x + bi.x;
        float o1 = (v[i].y - mu) * rstd * sc.y + bi.y;
        float o2 = (v[i].z - mu) * rstd * sc.z + bi.z;
        float o3 = (v[i].w - mu) * rstd * sc.w + bi.w;
        __half2 p0 = {__float2half_rn(o0), __float2half_rn(o1)};
        __half2 p1 = {__float2half_rn(o2), __float2half_rn(o3)};
        *(__half2*)&out[base + c + 0] = p0;
        *(__half2*)&out[base + c + 2] = p1;
    }
}

__global__ void prep_kernel(const float* __restrict__ wq, const float* __restrict__ wk,
                            const float* __restrict__ wv, const float* __restrict__ wo,
                            const float* __restrict__ w1, const float* __restrict__ w2,
                            __half* __restrict__ oqkv, __half* __restrict__ owo,
                            __half* __restrict__ ow1, __half* __restrict__ ow2,
                            const float* __restrict__ inputs,
                            const float* __restrict__ ln1_s, const float* __restrict__ ln1_b,
                            __half* __restrict__ xin)
{
    if (blockIdx.x >= WCONV_BLOCKS) {
        int token = ((blockIdx.x - WCONV_BLOCKS) * 256 + threadIdx.x) >> 5;
        if (token < TOK)
            ln_row_f16(inputs, ln1_s, ln1_b, xin, token, threadIdx.x & 31);
        return;
    }
    const int n1 = DMODEL*DMODEL, nm = DMODEL*MLPD;
    int i = (blockIdx.x * 256 + threadIdx.x) * 4;
    const float* src; __half* dst;
    if (i < 3*n1) {
        int seg = i / n1, j = i - seg * n1;
        src = (seg == 0) ? wq : (seg == 1) ? wk : wv;
        int k = j / DMODEL, n = j % DMODEL;
        size_t doff = (size_t)k * QKVN + seg * 512 + n;
        float4 v = *(const float4*)&src[j];
        __half2 p0 = {__float2half_rn(v.x), __float2half_rn(v.y)};
        __half2 p1 = {__float2half_rn(v.z), __float2half_rn(v.w)};
        *(__half2*)&oqkv[doff]   = p0;
        *(__half2*)&oqkv[doff+2] = p1;
        return;
    }
    i -= 3*n1;
    if (i < n1)            { src = wo; dst = owo; }
    else if (i < n1 + nm)  { src = w1; dst = ow1; i -= n1; }
    else                   { src = w2; dst = ow2; i -= n1 + nm; }
    float4 v = *(const float4*)&src[i];
    __half2 p0 = {__float2half_rn(v.x), __float2half_rn(v.y)};
    __half2 p1 = {__float2half_rn(v.z), __float2half_rn(v.w)};
    *(__half2*)&dst[i]   = p0;
    *(__half2*)&dst[i+2] = p1;
}

// ================= LayerNorm -> fp16 (standalone, for LN2) =================
__global__ void ln_h_kernel(const float* __restrict__ x,
                            const float* __restrict__ scale,
                            const float* __restrict__ bias,
                            __half* __restrict__ out)
{
    int token = (blockIdx.x * blockDim.x + threadIdx.x) >> 5;
    if (token >= TOK) return;
    ln_row_f16(x, scale, bias, out, token, threadIdx.x & 31);
}

// ================= HMMA fp16 persistent GEMM (3 CTAs/SM, warp tile 64x32) =================
// CTA tile 128x64, 4 warps in 2m x 2n, KT=32, 5 stages.
#define KT 32
#define GSTAGES 5
#define A_STRIDE 40            // halfs per A row (80B, conflict-free)
#define B_STRIDE 72            // halfs per B row (144B, conflict-free — attention-verified)
#define A_BYTES (128 * A_STRIDE * 2)        // 10240
#define B_BYTES (KT * B_STRIDE * 2)         // 4608
#define STAGE_BYTES (A_BYTES + B_BYTES)     // 14848
#define GEMM_SMEM (GSTAGES * STAGE_BYTES)   // 74240 -> 3 CTAs/SM

template<int BIAS, int GELU, int RES, int HOUT>
__global__ __launch_bounds__(128, 3)
void mma_gemm(const __half* __restrict__ A, const __half* __restrict__ B,
              const float* __restrict__ bias, const float* __restrict__ res,
              float* __restrict__ Cf, __half* __restrict__ Ch,
              int M, int N, int K)
{
    extern __shared__ char smembuf[];
    const uint32_t sbase = smem_cast(smembuf);
    const int tid = threadIdx.x, warp = tid >> 5, lane = tid & 31;
    const int T = K / KT;
    const int wm = (warp >> 1) * 64;      // 2 warps in m (128 rows)
    const int wn = (warp & 1) * 32;       // 2 warps in n (64 cols)
    const int ntn = N / 64;
    const int nt = (M / 128) * ntn;

    // loaders: A 512 chunks (4/thread), B 256 chunks (2/thread)
    const int a_row = tid >> 2, a_kc = tid & 3;      // + q*32 rows
    const int b_row = tid >> 3, b_nc = tid & 7;      // chunks tid, tid+128 -> rows +16

    const uint32_t a_off = ((wm + (lane & 15)) * A_STRIDE + (lane >> 4) * 8) * 2;
    const uint32_t b_off = (((lane & 15)) * B_STRIDE + wn + (lane >> 4) * 8) * 2;

    for (int tile = blockIdx.x; tile < nt; tile += GRID_P3) {
        const int m0 = (tile / ntn) * 128;
        const int n0 = (tile % ntn) * 64;

        float acc[4][4][4];
#pragma unroll
        for (int i = 0; i < 4; i++)
#pragma unroll
            for (int j = 0; j < 4; j++)
#pragma unroll
                for (int q = 0; q < 4; q++) acc[i][j][q] = 0.f;

        auto issue = [&](int it) {
            int kk = it * KT;
            uint32_t sA = sbase + (uint32_t)(it % GSTAGES) * STAGE_BYTES;
            uint32_t sB = sA + A_BYTES;
#pragma unroll
            for (int q = 0; q < 4; q++) {
                int row = a_row + q * 32;
                cp16(sA + row * (A_STRIDE * 2) + a_kc * 16,
                     A + (size_t)(m0 + row) * K + kk + a_kc * 8);
            }
#pragma unroll
            for (int q = 0; q < 2; q++) {
                int row = b_row + q * 16;
                cp16(sB + row * (B_STRIDE * 2) + b_nc * 16,
                     B + (size_t)(kk + row) * N + n0 + b_nc * 8);
            }
            CP_COMMIT();
        };

        __syncthreads();   // previous tile done with smem

#pragma unroll
        for (int s = 0; s < GSTAGES - 1; s++) issue(s);

        uint32_t af[2][4][4], bf[2][2][4];

        for (int it = 0; it < T; it++) {
            CP_WAIT(3);
            __syncthreads();
            if (it + GSTAGES - 1 < T) issue(it + GSTAGES - 1);
            else CP_COMMIT();

            uint32_t sA = sbase + (uint32_t)(it % GSTAGES) * STAGE_BYTES;
            uint32_t sB = sA + A_BYTES;

#pragma unroll
            for (int mi = 0; mi < 4; mi++)
                ldsm4(af[0][mi], sA + a_off + (mi * 16 * A_STRIDE) * 2);
#pragma unroll
            for (int bi = 0; bi < 2; bi++)
                ldsm4t(bf[0][bi], sB + b_off + (bi * 16) * 2);
#pragma unroll
            for (int mi = 0; mi < 4; mi++)
                ldsm4(af[1][mi], sA + a_off + (mi * 16 * A_STRIDE + 16) * 2);
#pragma unroll
            for (int bi = 0; bi < 2; bi++)
                ldsm4t(bf[1][bi], sB + b_off + (16 * B_STRIDE + bi * 16) * 2);

#pragma unroll
            for (int ks = 0; ks < 2; ks++)
#pragma unroll
                for (int mi = 0; mi < 4; mi++)
#pragma unroll
                    for (int ni = 0; ni < 4; ni++)
                        mma16816(acc[mi][ni], af[ks][mi], &bf[ks][ni >> 1][(ni & 1) * 2]);
        }

#pragma unroll
        for (int mi = 0; mi < 4; mi++) {
#pragma unroll
            for (int r = 0; r < 2; r++) {
                int row = m0 + wm + mi * 16 + r * 8 + (lane >> 2);
#pragma unroll
                for (int ni = 0; ni < 4; ni++) {
                    int col = n0 + wn + ni * 8 + (lane & 3) * 2;
                    size_t off = (size_t)row * N + col;
                    float v0 = acc[mi][ni][r * 2 + 0];
                    float v1 = acc[mi][ni][r * 2 + 1];
                    if (BIAS) { v0 += bias[col]; v1 += bias[col + 1]; }
                    if (GELU) { v0 = gelu_f(v0); v1 = gelu_f(v1); }
                    if (RES)  { float2 rr = *(const float2*)&res[off]; v0 += rr.x; v1 += rr.y; }
                    if (HOUT) {
                        __half2 hh = {__float2half_rn(v0), __float2half_rn(v1)};
                        *(__half2*)&Ch[off] = hh;
                    } else {
                        float2 o = {v0, v1};
                        *(float2*)&Cf[off] = o;
                    }
                }
            }
        }
    }
}

// ================= HMMA block-local attention (verified) =================
#define AT_STRIDE 72
#define ATTN_SMEM (3 * BS * AT_STRIDE * 2)

__global__ __launch_bounds__(128, 2)
void attn_mma_kernel(const __half* __restrict__ qkv, __half* __restrict__ ctx)
{
    extern __shared__ char smemraw[];
    const uint32_t sbase = smem_cast(smemraw);
    const uint32_t qs = sbase;
    const uint32_t ks = sbase + BS * AT_STRIDE * 2;
    const uint32_t vs = ks   + BS * AT_STRIDE * 2;

    int bid = blockIdx.x;
    int h   = bid & 7;
    int blk = (bid >> 3) & 31;
    int b   = bid >> 8;
    int t0  = b * 4096 + blk * BS;
    int tid = threadIdx.x, warp = tid >> 5, lane = tid & 31;

#pragma unroll
    for (int q = 0; q < 8; q++) {
        int cc = tid + q * 128;
        int row = cc >> 3, ch = cc & 7;
        const __half* src = qkv + (size_t)(t0 + row) * QKVN + h * 64 + ch * 8;
        uint32_t doff = row * (AT_STRIDE * 2) + ch * 16;
        cp16(qs + doff, src);
        cp16(ks + doff, src + 512);
        cp16(vs + doff, src + 1024);
    }
    CP_COMMIT();
    CP_WAIT(0);
    __syncthreads();

    const int wm = warp * 32;

    float accs[2][16][4];
#pragma unroll
    for (int i = 0; i < 2; i++)
#pragma unroll
        for (int j = 0; j < 16; j++)
#pragma unroll
            for (int q = 0; q < 4; q++) accs[i][j][q] = 0.f;

#pragma unroll
    for (int kt = 0; kt < 4; kt++) {
        uint32_t aq[2][4];
#pragma unroll
        for (int mi = 0; mi < 2; mi++)
            ldsm4(aq[mi], qs + (((wm + mi*16 + (lane & 15)) * AT_STRIDE)
                                + kt*16 + (lane >> 4) * 8) * 2);
#pragma unroll
        for (int pr = 0; pr < 8; pr++) {
            uint32_t bk[4];
            ldsm4(bk, ks + (((pr*16 + (lane & 15)) * AT_STRIDE)
                            + kt*16 + (lane >> 4) * 8) * 2);
            uint32_t b0[2] = {bk[0], bk[2]};
            uint32_t b1[2] = {bk[1], bk[3]};
#pragma unroll
            for (int mi = 0; mi < 2; mi++) {
                mma16816(accs[mi][2*pr + 0], aq[mi], b0);
                mma16816(accs[mi][2*pr + 1], aq[mi], b1);
            }
        }
    }

    const float C = 0.125f * 1.4426950408889634f;
    uint32_t ph[2][16][2];
    float inv0[2], inv1[2];
#pragma unroll
    for (int mi = 0; mi < 2; mi++) {
        float mx0 = -1e30f, mx1 = -1e30f;
#pragma unroll
        for (int ni = 0; ni < 16; ni++) {
            mx0 = fmaxf(mx0, fmaxf(accs[mi][ni][0], accs[mi][ni][1]));
            mx1 = fmaxf(mx1, fmaxf(accs[mi][ni][2], accs[mi][ni][3]));
        }
        mx0 = fmaxf(mx0, __shfl_xor_sync(0xffffffffu, mx0, 1));
        mx0 = fmaxf(mx0, __shfl_xor_sync(0xffffffffu, mx0, 2));
        mx1 = fmaxf(mx1, __shfl_xor_sync(0xffffffffu, mx1, 1));
        mx1 = fmaxf(mx1, __shfl_xor_sync(0xffffffffu, mx1, 2));

        float s0 = 0.f, s1 = 0.f;
#pragma unroll
        for (int ni = 0; ni < 16; ni++) {
            __half2 e0 = h2exp2(__floats2half2_rn((accs[mi][ni][0] - mx0) * C,
                                                  (accs[mi][ni][1] - mx0) * C));
            __half2 e1 = h2exp2(__floats2half2_rn((accs[mi][ni][2] - mx1) * C,
                                                  (accs[mi][ni][3] - mx1) * C));
            ph[mi][ni][0] = *(uint32_t*)&e0;
            ph[mi][ni][1] = *(uint32_t*)&e1;
            float2 f0 = __half22float2(e0);
            float2 f1 = __half22float2(e1);
            s0 += f0.x + f0.y;
            s1 += f1.x + f1.y;
        }
        s0 += __shfl_xor_sync(0xffffffffu, s0, 1);
        s0 += __shfl_xor_sync(0xffffffffu, s0, 2);
        s1 += __shfl_xor_sync(0xffffffffu, s1, 1);
        s1 += __shfl_xor_sync(0xffffffffu, s1, 2);
        inv0[mi] = 1.f / s0;
        inv1[mi] = 1.f / s1;
    }

    float acco[2][8][4];
#pragma unroll
    for (int i = 0; i < 2; i++)
#pragma unroll
        for (int j = 0; j < 8; j++)
#pragma unroll
            for (int q = 0; q < 4; q++) acco[i][j][q] = 0.f;

#pragma unroll
    for (int kt = 0; kt < 8; kt++) {
        uint32_t bv[4][4];
#pragma unroll
        for (int bi = 0; bi < 4; bi++)
            ldsm4t(bv[bi], vs + (((kt*16 + (lane & 15)) * AT_STRIDE)
                                 + bi*16 + (lane >> 4) * 8) * 2);
#pragma unroll
        for (int mi = 0; mi < 2; mi++) {
            uint32_t a[4] = {ph[mi][2*kt][0], ph[mi][2*kt][1],
                             ph[mi][2*kt+1][0], ph[mi][2*kt+1][1]};
#pragma unroll
            for (int ni = 0; ni < 8; ni++)
                mma16816(acco[mi][ni], a, &bv[ni >> 1][(ni & 1) * 2]);
        }
    }

#pragma unroll
    for (int mi = 0; mi < 2; mi++) {
#pragma unroll
        for (int r = 0; r < 2; r++) {
            int row = t0 + wm + mi*16 + r*8 + (lane >> 2);
            float iv = r ? inv1[mi] : inv0[mi];
#pragma unroll
            for (int ni = 0; ni < 8; ni++) {
                int col = h*64 + ni*8 + (lane & 3) * 2;
                __half2 hh = {__float2half_rn(acco[mi][ni][r*2 + 0] * iv),
                              __float2half_rn(acco[mi][ni][r*2 + 1] * iv)};
                *(__half2*)&ctx[(size_t)row * DMODEL + col] = hh;
            }
        }
    }
}

// ================= launch =================
extern "C" void kernel_launch(void* const* d_in, const int* in_sizes, int n_in,
                              void* d_out, int out_size)
{
    const float* inputs = (const float*)d_in[0];
    const float* ln1_s  = (const float*)d_in[1];
    const float* ln1_b  = (const float*)d_in[2];
    const float* wq     = (const float*)d_in[3];
    const float* wk     = (const float*)d_in[4];
    const float* wv     = (const float*)d_in[5];
    const float* wo     = (const float*)d_in[6];
    const float* ln2_s  = (const float*)d_in[7];
    const float* ln2_b  = (const float*)d_in[8];
    const float* w1     = (const float*)d_in[9];
    const float* b1     = (const float*)d_in[10];
    const float* w2     = (const float*)d_in[11];
    const float* b2     = (const float*)d_in[12];
    float* out = (float*)d_out;

    void *xin, *qkv, *ctx, *xb, *yb, *hb;
    void *wqkvp, *wop, *w1p, *w2p;
    cudaGetSymbolAddress(&xin, g_xin); cudaGetSymbolAddress(&qkv, g_qkv);
    cudaGetSymbolAddress(&ctx, g_ctx); cudaGetSymbolAddress(&xb, g_x);
    cudaGetSymbolAddress(&yb, g_y);    cudaGetSymbolAddress(&hb, g_h);
    cudaGetSymbolAddress(&wqkvp, g_wqkv); cudaGetSymbolAddress(&wop, g_wo);
    cudaGetSymbolAddress(&w1p, g_w1);     cudaGetSymbolAddress(&w2p, g_w2);

    cudaFuncSetAttribute(mma_gemm<0,0,0,1>, cudaFuncAttributeMaxDynamicSharedMemorySize, GEMM_SMEM);
    cudaFuncSetAttribute(mma_gemm<0,0,1,0>, cudaFuncAttributeMaxDynamicSharedMemorySize, GEMM_SMEM);
    cudaFuncSetAttribute(mma_gemm<1,1,0,1>, cudaFuncAttributeMaxDynamicSharedMemorySize, GEMM_SMEM);
    cudaFuncSetAttribute(mma_gemm<1,0,1,0>, cudaFuncAttributeMaxDynamicSharedMemorySize, GEMM_SMEM);
    cudaFuncSetAttribute(attn_mma_kernel, cudaFuncAttributeMaxDynamicSharedMemorySize, ATTN_SMEM);

    // 0+1. fused prep: weight conversion || LN1
    prep_kernel<<<PREP_BLOCKS, 256>>>(wq, wk, wv, wo, w1, w2,
        (__half*)wqkvp, (__half*)wop, (__half*)w1p, (__half*)w2p,
        inputs, ln1_s, ln1_b, (__half*)xin);

    // 2. fused QKV -> fp16  (M=TOK, N=1536, K=512)
    mma_gemm<0,0,0,1><<<GRID_P3, 128, GEMM_SMEM>>>((__half*)xin, (__half*)wqkvp,
        nullptr, nullptr, nullptr, (__half*)qkv, TOK, QKVN, DMODEL);

    // 3. attention (HMMA)
    attn_mma_kernel<<<4 * NBLK * NH, 128, ATTN_SMEM>>>((const __half*)qkv, (__half*)ctx);

    // 4. O proj + residual -> x (fp32)
    mma_gemm<0,0,1,0><<<GRID_P3, 128, GEMM_SMEM>>>((__half*)ctx, (__half*)wop,
        nullptr, inputs, (float*)xb, nullptr, TOK, DMODEL, DMODEL);

    // 5. LN2 -> fp16
    ln_h_kernel<<<TOK/8, 256>>>((const float*)xb, ln2_s, ln2_b, (__half*)yb);

    // 6. MLP up + bias + gelu -> fp16 h  (N=2048, K=512)
    mma_gemm<1,1,0,1><<<GRID_P3, 128, GEMM_SMEM>>>((__half*)yb, (__half*)w1p,
        b1, nullptr, nullptr, (__half*)hb, TOK, MLPD, DMODEL);

    // 7. MLP down + bias + residual -> out  (N=512, K=2048)
    mma_gemm<1,0,1,0><<<GRID_P3, 128, GEMM_SMEM>>>((__half*)hb, (__half*)w2p,
        b2, (const float*)xb, out, nullptr, TOK, DMODEL, MLPD);
}

// round 15
// speedup vs baseline: 1.1202x; 1.1202x over previous
#include <cuda_runtime.h>
#include <cuda_fp16.h>
#include <math.h>
#include <stdint.h>

#define TOK   (4*4096)
#define DMODEL 512
#define QKVN  1536
#define MLPD   2048
#define NH     8
#define DH     64
#define BS     128
#define NBLK   32
#define GRID_P 296        // 148 SMs x 2 CTAs

// ================= scratch =================
__device__ __half g_xin[TOK*DMODEL];
__device__ __half g_qkv[TOK*QKVN];
__device__ __half g_ctx[TOK*DMODEL];
__device__ float  g_x  [TOK*DMODEL];
__device__ __half g_y  [TOK*DMODEL];
__device__ __half g_h  [TOK*MLPD];
__device__ __half g_wqkv[DMODEL*QKVN];
__device__ __half g_wo  [DMODEL*DMODEL];
__device__ __half g_w1  [DMODEL*MLPD];
__device__ __half g_w2  [MLPD*DMODEL];

// ================= small helpers =================
__device__ __forceinline__ uint32_t smem_cast(const void* p) {
    return (uint32_t)__cvta_generic_to_shared(p);
}
__device__ __forceinline__ void cp16(uint32_t s, const void* g) {
    asm volatile("cp.async.cg.shared.global [%0], [%1], 16;" :: "r"(s), "l"(g));
}
#define CP_COMMIT() asm volatile("cp.async.commit_group;")
#define CP_WAIT(n)  asm volatile("cp.async.wait_group %0;" :: "n"(n))

__device__ __forceinline__ void ldsm4(uint32_t* r, uint32_t a) {
    asm volatile("ldmatrix.sync.aligned.m8n8.x4.shared.b16 {%0,%1,%2,%3}, [%4];"
                 : "=r"(r[0]), "=r"(r[1]), "=r"(r[2]), "=r"(r[3]) : "r"(a));
}
__device__ __forceinline__ void ldsm4t(uint32_t* r, uint32_t a) {
    asm volatile("ldmatrix.sync.aligned.m8n8.x4.trans.shared.b16 {%0,%1,%2,%3}, [%4];"
                 : "=r"(r[0]), "=r"(r[1]), "=r"(r[2]), "=r"(r[3]) : "r"(a));
}
__device__ __forceinline__ void mma16816(float* d, const uint32_t* a, const uint32_t* b) {
    asm volatile("mma.sync.aligned.m16n8k16.row.col.f32.f16.f16.f32 "
                 "{%0,%1,%2,%3},{%4,%5,%6,%7},{%8,%9},{%0,%1,%2,%3};"
                 : "+f"(d[0]), "+f"(d[1]), "+f"(d[2]), "+f"(d[3])
                 : "r"(a[0]), "r"(a[1]), "r"(a[2]), "r"(a[3]), "r"(b[0]), "r"(b[1]));
}

__device__ __forceinline__ float gelu_f(float x) {
    float x3 = x * x * x;
    return 0.5f * x * (1.0f + tanhf(0.7978845608028654f * (x + 0.044715f * x3)));
}

// ================= fused prep: weight conversion + LN1 in ONE launch =================
#define WCONV_ELEMS (4*DMODEL*DMODEL + 2*DMODEL*MLPD)
#define WCONV_BLOCKS (WCONV_ELEMS / 4 / 256)
#define LN1_BLOCKS (TOK / 8)
#define PREP_BLOCKS (WCONV_BLOCKS + LN1_BLOCKS)

__device__ __forceinline__ void ln_row_f16(const float* __restrict__ x,
                                           const float* __restrict__ scale,
                                           const float* __restrict__ bias,
                                           __half* __restrict__ out,
                                           int token, int lane)
{
    const float* row = x + (size_t)token * DMODEL;
    float4 v[4];
    float sum = 0.f;
#pragma unroll
    for (int i = 0; i < 4; i++) {
        v[i] = *(const float4*)&row[lane*4 + i*128];
        sum += v[i].x + v[i].y + v[i].z + v[i].w;
    }
#pragma unroll
    for (int o = 16; o; o >>= 1) sum += __shfl_xor_sync(0xffffffffu, sum, o);
    float mu = sum * (1.0f / DMODEL);
    float var = 0.f;
#pragma unroll
    for (int i = 0; i < 4; i++) {
        float dx = v[i].x - mu, dy = v[i].y - mu, dz = v[i].z - mu, dw = v[i].w - mu;
        var += dx*dx + dy*dy + dz*dz + dw*dw;
    }
#pragma unroll
    for (int o = 16; o; o >>= 1) var += __shfl_xor_sync(0xffffffffu, var, o);
    float rstd = rsqrtf(var * (1.0f / DMODEL) + 1e-6f);

    size_t base = (size_t)token * DMODEL;
#pragma unroll
    for (int i = 0; i < 4; i++) {
        int c = lane*4 + i*128;
        float4 sc = *(const float4*)&scale[c];
        float4 bi = *(const float4*)&bias[c];
        float o0 = (v[i].x - mu) * rstd * sc.x + bi.x;
        float o1 = (v[i].y - mu) * rstd * sc.y + bi.y;
        float o2 = (v[i].z - mu) * rstd * sc.z + bi.z;
        float o3 = (v[i].w - mu) * rstd * sc.w + bi.w;
        __half2 p0 = {__float2half_rn(o0), __float2half_rn(o1)};
        __half2 p1 = {__float2half_rn(o2), __float2half_rn(o3)};
        *(__half2*)&out[base + c + 0] = p0;
        *(__half2*)&out[base + c + 2] = p1;
    }
}

__global__ void prep_kernel(const float* __restrict__ wq, const float* __restrict__ wk,
                            const float* __restrict__ wv, const float* __restrict__ wo,
                            const float* __restrict__ w1, const float* __restrict__ w2,
                            __half* __restrict__ oqkv, __half* __restrict__ owo,
                            __half* __restrict__ ow1, __half* __restrict__ ow2,
                            const float* __restrict__ inputs,
                            const float* __restrict__ ln1_s, const float* __restrict__ ln1_b,
                            __half* __restrict__ xin)
{
    if (blockIdx.x >= WCONV_BLOCKS) {
        int token = ((blockIdx.x - WCONV_BLOCKS) * 256 + threadIdx.x) >> 5;
        if (token < TOK)
            ln_row_f16(inputs, ln1_s, ln1_b, xin, token, threadIdx.x & 31);
        return;
    }
    const int n1 = DMODEL*DMODEL, nm = DMODEL*MLPD;
    int i = (blockIdx.x * 256 + threadIdx.x) * 4;
    const float* src; __half* dst;
    if (i < 3*n1) {
        int seg = i / n1, j = i - seg * n1;
        src = (seg == 0) ? wq : (seg == 1) ? wk : wv;
        int k = j / DMODEL, n = j % DMODEL;
        size_t doff = (size_t)k * QKVN + seg * 512 + n;
        float4 v = *(const float4*)&src[j];
        __half2 p0 = {__float2half_rn(v.x), __float2half_rn(v.y)};
        __half2 p1 = {__float2half_rn(v.z), __float2half_rn(v.w)};
        *(__half2*)&oqkv[doff]   = p0;
        *(__half2*)&oqkv[doff+2] = p1;
        return;
    }
    i -= 3*n1;
    if (i < n1)            { src = wo; dst = owo; }
    else if (i < n1 + nm)  { src = w1; dst = ow1; i -= n1; }
    else                   { src = w2; dst = ow2; i -= n1 + nm; }
    float4 v = *(const float4*)&src[i];
    __half2 p0 = {__float2half_rn(v.x), __float2half_rn(v.y)};
    __half2 p1 = {__float2half_rn(v.z), __float2half_rn(v.w)};
    *(__half2*)&dst[i]   = p0;
    *(__half2*)&dst[i+2] = p1;
}

// ================= LayerNorm -> fp16 (standalone, for LN2) =================
__global__ void ln_h_kernel(const float* __restrict__ x,
                            const float* __restrict__ scale,
                            const float* __restrict__ bias,
                            __half* __restrict__ out)
{
    int token = (blockIdx.x * blockDim.x + threadIdx.x) >> 5;
    if (token >= TOK) return;
    ln_row_f16(x, scale, bias, out, token, threadIdx.x & 31);
}

// ================= HMMA fp16 persistent GEMM (R11 optimum: 128x128, 64x64 warp, KT=32) =================
#define KT 32
#define GSTAGES 5
#define A_STRIDE 40
#define B_STRIDE 136
#define A_BYTES (128 * A_STRIDE * 2)
#define B_BYTES (KT * B_STRIDE * 2)
#define STAGE_BYTES (A_BYTES + B_BYTES)
#define GEMM_SMEM (GSTAGES * STAGE_BYTES)

template<int BIAS, int GELU, int RES, int HOUT>
__global__ __launch_bounds__(128, 2)
void mma_gemm(const __half* __restrict__ A, const __half* __restrict__ B,
              const float* __restrict__ bias, const float* __restrict__ res,
              float* __restrict__ Cf, __half* __restrict__ Ch,
              int M, int N, int K)
{
    extern __shared__ char smembuf[];
    const uint32_t sbase = smem_cast(smembuf);
    const int tid = threadIdx.x, warp = tid >> 5, lane = tid & 31;
    const int T = K / KT;
    const int wm = (warp >> 1) * 64;
    const int wn = (warp & 1) * 64;
    const int ntn = N / 128;
    const int nt = (M / 128) * ntn;

    const int a_row = tid >> 2, a_kc = tid & 3;
    const int b_row = tid >> 4, b_nc = tid & 15;

    const uint32_t a_off = ((wm + (lane & 15)) * A_STRIDE + (lane >> 4) * 8) * 2;
    const uint32_t b_off = (((lane & 15)) * B_STRIDE + wn + (lane >> 4) * 8) * 2;

    for (int tile = blockIdx.x; tile < nt; tile += GRID_P) {
        const int m0 = (tile / ntn) * 128;
        const int n0 = (tile % ntn) * 128;

        float acc[4][8][4];
#pragma unroll
        for (int i = 0; i < 4; i++)
#pragma unroll
            for (int j = 0; j < 8; j++)
#pragma unroll
                for (int q = 0; q < 4; q++) acc[i][j][q] = 0.f;

        auto issue = [&](int it) {
            int kk = it * KT;
            uint32_t sA = sbase + (uint32_t)(it % GSTAGES) * STAGE_BYTES;
            uint32_t sB = sA + A_BYTES;
#pragma unroll
            for (int q = 0; q < 4; q++) {
                int row = a_row + q * 32;
                cp16(sA + row * (A_STRIDE * 2) + a_kc * 16,
                     A + (size_t)(m0 + row) * K + kk + a_kc * 8);
            }
#pragma unroll
            for (int q = 0; q < 4; q++) {
                int row = b_row + q * 8;
                cp16(sB + row * (B_STRIDE * 2) + b_nc * 16,
                     B + (size_t)(kk + row) * N + n0 + b_nc * 8);
            }
            CP_COMMIT();
        };

        __syncthreads();

#pragma unroll
        for (int s = 0; s < GSTAGES - 1; s++) issue(s);

        uint32_t af[2][4][4], bf[2][4][4];

        for (int it = 0; it < T; it++) {
            CP_WAIT(3);
            __syncthreads();
            if (it + GSTAGES - 1 < T) issue(it + GSTAGES - 1);
            else CP_COMMIT();

            uint32_t sA = sbase + (uint32_t)(it % GSTAGES) * STAGE_BYTES;
            uint32_t sB = sA + A_BYTES;

#pragma unroll
            for (int mi = 0; mi < 4; mi++)
                ldsm4(af[0][mi], sA + a_off + (mi * 16 * A_STRIDE) * 2);
#pragma unroll
            for (int bi = 0; bi < 4; bi++)
                ldsm4t(bf[0][bi], sB + b_off + (bi * 16) * 2);
#pragma unroll
            for (int mi = 0; mi < 4; mi++)
                ldsm4(af[1][mi], sA + a_off + (mi * 16 * A_STRIDE + 16) * 2);
#pragma unroll
            for (int bi = 0; bi < 4; bi++)
                ldsm4t(bf[1][bi], sB + b_off + (16 * B_STRIDE + bi * 16) * 2);

#pragma unroll
            for (int ks = 0; ks < 2; ks++)
#pragma unroll
                for (int mi = 0; mi < 4; mi++)
#pragma unroll
                    for (int ni = 0; ni < 8; ni++)
                        mma16816(acc[mi][ni], af[ks][mi], &bf[ks][ni >> 1][(ni & 1) * 2]);
        }

#pragma unroll
        for (int mi = 0; mi < 4; mi++) {
#pragma unroll
            for (int r = 0; r < 2; r++) {
                int row = m0 + wm + mi * 16 + r * 8 + (lane >> 2);
#pragma unroll
                for (int ni = 0; ni < 8; ni++) {
                    int col = n0 + wn + ni * 8 + (lane & 3) * 2;
                    size_t off = (size_t)row * N + col;
                    float v0 = acc[mi][ni][r * 2 + 0];
                    float v1 = acc[mi][ni][r * 2 + 1];
                    if (BIAS) { v0 += bias[col]; v1 += bias[col + 1]; }
                    if (GELU) { v0 = gelu_f(v0); v1 = gelu_f(v1); }
                    if (RES)  { float2 rr = *(const float2*)&res[off]; v0 += rr.x; v1 += rr.y; }
                    if (HOUT) {
                        __half2 hh = {__float2half_rn(v0), __float2half_rn(v1)};
                        *(__half2*)&Ch[off] = hh;
                    } else {
                        float2 o = {v0, v1};
                        *(float2*)&Cf[off] = o;
                    }
                }
            }
        }
    }
}

// ================= HMMA block-local attention (verified, 31.4us) =================
#define AT_STRIDE 72
#define ATTN_SMEM (3 * BS * AT_STRIDE * 2)

__global__ __launch_bounds__(128, 2)
void attn_mma_kernel(const __half* __restrict__ qkv, __half* __restrict__ ctx)
{
    extern __shared__ char smemraw[];
    const uint32_t sbase = smem_cast(smemraw);
    const uint32_t qs = sbase;
    const uint32_t ks = sbase + BS * AT_STRIDE * 2;
    const uint32_t vs = ks   + BS * AT_STRIDE * 2;

    int bid = blockIdx.x;
    int h   = bid & 7;
    int blk = (bid >> 3) & 31;
    int b   = bid >> 8;
    int t0  = b * 4096 + blk * BS;
    int tid = threadIdx.x, warp = tid >> 5, lane = tid & 31;

#pragma unroll
    for (int q = 0; q < 8; q++) {
        int cc = tid + q * 128;
        int row = cc >> 3, ch = cc & 7;
        const __half* src = qkv + (size_t)(t0 + row) * QKVN + h * 64 + ch * 8;
        uint32_t doff = row * (AT_STRIDE * 2) + ch * 16;
        cp16(qs + doff, src);
        cp16(ks + doff, src + 512);
        cp16(vs + doff, src + 1024);
    }
    CP_COMMIT();
    CP_WAIT(0);
    __syncthreads();

    const int wm = warp * 32;

    float accs[2][16][4];
#pragma unroll
    for (int i = 0; i < 2; i++)
#pragma unroll
        for (int j = 0; j < 16; j++)
#pragma unroll
            for (int q = 0; q < 4; q++) accs[i][j][q] = 0.f;

#pragma unroll
    for (int kt = 0; kt < 4; kt++) {
        uint32_t aq[2][4];
#pragma unroll
        for (int mi = 0; mi < 2; mi++)
            ldsm4(aq[mi], qs + (((wm + mi*16 + (lane & 15)) * AT_STRIDE)
                                + kt*16 + (lane >> 4) * 8) * 2);
#pragma unroll
        for (int pr = 0; pr < 8; pr++) {
            uint32_t bk[4];
            ldsm4(bk, ks + (((pr*16 + (lane & 15)) * AT_STRIDE)
                            + kt*16 + (lane >> 4) * 8) * 2);
            uint32_t b0[2] = {bk[0], bk[2]};
            uint32_t b1[2] = {bk[1], bk[3]};
#pragma unroll
            for (int mi = 0; mi < 2; mi++) {
                mma16816(accs[mi][2*pr + 0], aq[mi], b0);
                mma16816(accs[mi][2*pr + 1], aq[mi], b1);
            }
        }
    }

    const float C = 0.125f * 1.4426950408889634f;
    uint32_t ph[2][16][2];
    float inv0[2], inv1[2];
#pragma unroll
    for (int mi = 0; mi < 2; mi++) {
        float mx0 = -1e30f, mx1 = -1e30f;
#pragma unroll
        for (int ni = 0; ni < 16; ni++) {
            mx0 = fmaxf(mx0, fmaxf(accs[mi][ni][0], accs[mi][ni][1]));
            mx1 = fmaxf(mx1, fmaxf(accs[mi][ni][2], accs[mi][ni][3]));
        }
        mx0 = fmaxf(mx0, __shfl_xor_sync(0xffffffffu, mx0, 1));
        mx0 = fmaxf(mx0, __shfl_xor_sync(0xffffffffu, mx0, 2));
        mx1 = fmaxf(mx1, __shfl_xor_sync(0xffffffffu, mx1, 1));
        mx1 = fmaxf(mx1, __shfl_xor_sync(0xffffffffu, mx1, 2));

        float s0 = 0.f, s1 = 0.f;
#pragma unroll
        for (int ni = 0; ni < 16; ni++) {
            __half2 e0 = h2exp2(__floats2half2_rn((accs[mi][ni][0] - mx0) * C,
                                                  (accs[mi][ni][1] - mx0) * C));
            __half2 e1 = h2exp2(__floats2half2_rn((accs[mi][ni][2] - mx1) * C,
                                                  (accs[mi][ni][3] - mx1) * C));
            ph[mi][ni][0] = *(uint32_t*)&e0;
            ph[mi][ni][1] = *(uint32_t*)&e1;
            float2 f0 = __half22float2(e0);
            float2 f1 = __half22float2(e1);
            s0 += f0.x + f0.y;
            s1 += f1.x + f1.y;
        }
        s0 += __shfl_xor_sync(0xffffffffu, s0, 1);
        s0 += __shfl_xor_sync(0xffffffffu, s0, 2);
        s1 += __shfl_xor_sync(0xffffffffu, s1, 1);
        s1 += __shfl_xor_sync(0xffffffffu, s1, 2);
        inv0[mi] = 1.f / s0;
        inv1[mi] = 1.f / s1;
    }

    float acco[2][8][4];
#pragma unroll
    for (int i = 0; i < 2; i++)
#pragma unroll
        for (int j = 0; j < 8; j++)
#pragma unroll
            for (int q = 0; q < 4; q++) acco[i][j][q] = 0.f;

#pragma unroll
    for (int kt = 0; kt < 8; kt++) {
        uint32_t bv[4][4];
#pragma unroll
        for (int bi = 0; bi < 4; bi++)
            ldsm4t(bv[bi], vs + (((kt*16 + (lane & 15)) * AT_STRIDE)
                                 + bi*16 + (lane >> 4) * 8) * 2);
#pragma unroll
        for (int mi = 0; mi < 2; mi++) {
            uint32_t a[4] = {ph[mi][2*kt][0], ph[mi][2*kt][1],
                             ph[mi][2*kt+1][0], ph[mi][2*kt+1][1]};
#pragma unroll
            for (int ni = 0; ni < 8; ni++)
                mma16816(acco[mi][ni], a, &bv[ni >> 1][(ni & 1) * 2]);
        }
    }

#pragma unroll
    for (int mi = 0; mi < 2; mi++) {
#pragma unroll
        for (int r = 0; r < 2; r++) {
            int row = t0 + wm + mi*16 + r*8 + (lane >> 2);
            float iv = r ? inv1[mi] : inv0[mi];
#pragma unroll
            for (int ni = 0; ni < 8; ni++) {
                int col = h*64 + ni*8 + (lane & 3) * 2;
                __half2 hh = {__float2half_rn(acco[mi][ni][r*2 + 0] * iv),
                              __float2half_rn(acco[mi][ni][r*2 + 1] * iv)};
                *(__half2*)&ctx[(size_t)row * DMODEL + col] = hh;
            }
        }
    }
}

// ================= launch =================
extern "C" void kernel_launch(void* const* d_in, const int* in_sizes, int n_in,
                              void* d_out, int out_size)
{
    const float* inputs = (const float*)d_in[0];
    const float* ln1_s  = (const float*)d_in[1];
    const float* ln1_b  = (const float*)d_in[2];
    const float* wq     = (const float*)d_in[3];
    const float* wk     = (const float*)d_in[4];
    const float* wv     = (const float*)d_in[5];
    const float* wo     = (const float*)d_in[6];
    const float* ln2_s  = (const float*)d_in[7];
    const float* ln2_b  = (const float*)d_in[8];
    const float* w1     = (const float*)d_in[9];
    const float* b1     = (const float*)d_in[10];
    const float* w2     = (const float*)d_in[11];
    const float* b2     = (const float*)d_in[12];
    float* out = (float*)d_out;

    void *xin, *qkv, *ctx, *xb, *yb, *hb;
    void *wqkvp, *wop, *w1p, *w2p;
    cudaGetSymbolAddress(&xin, g_xin); cudaGetSymbolAddress(&qkv, g_qkv);
    cudaGetSymbolAddress(&ctx, g_ctx); cudaGetSymbolAddress(&xb, g_x);
    cudaGetSymbolAddress(&yb, g_y);    cudaGetSymbolAddress(&hb, g_h);
    cudaGetSymbolAddress(&wqkvp, g_wqkv); cudaGetSymbolAddress(&wop, g_wo);
    cudaGetSymbolAddress(&w1p, g_w1);     cudaGetSymbolAddress(&w2p, g_w2);

    cudaFuncSetAttribute(mma_gemm<0,0,0,1>, cudaFuncAttributeMaxDynamicSharedMemorySize, GEMM_SMEM);
    cudaFuncSetAttribute(mma_gemm<0,0,1,0>, cudaFuncAttributeMaxDynamicSharedMemorySize, GEMM_SMEM);
    cudaFuncSetAttribute(mma_gemm<1,1,0,1>, cudaFuncAttributeMaxDynamicSharedMemorySize, GEMM_SMEM);
    cudaFuncSetAttribute(mma_gemm<1,0,1,0>, cudaFuncAttributeMaxDynamicSharedMemorySize, GEMM_SMEM);
    cudaFuncSetAttribute(attn_mma_kernel, cudaFuncAttributeMaxDynamicSharedMemorySize, ATTN_SMEM);

    // 0+1. fused prep: weight conversion || LN1
    prep_kernel<<<PREP_BLOCKS, 256>>>(wq, wk, wv, wo, w1, w2,
        (__half*)wqkvp, (__half*)wop, (__half*)w1p, (__half*)w2p,
        inputs, ln1_s, ln1_b, (__half*)xin);

    // 2. fused QKV -> fp16  (M=TOK, N=1536, K=512)
    mma_gemm<0,0,0,1><<<GRID_P, 128, GEMM_SMEM>>>((__half*)xin, (__half*)wqkvp,
        nullptr, nullptr, nullptr, (__half*)qkv, TOK, QKVN, DMODEL);

    // 3. attention (HMMA)
    attn_mma_kernel<<<4 * NBLK * NH, 128, ATTN_SMEM>>>((const __half*)qkv, (__half*)ctx);

    // 4. O proj + residual -> x (fp32)
    mma_gemm<0,0,1,0><<<GRID_P, 128, GEMM_SMEM>>>((__half*)ctx, (__half*)wop,
        nullptr, inputs, (float*)xb, nullptr, TOK, DMODEL, DMODEL);

    // 5. LN2 -> fp16
    ln_h_kernel<<<TOK/8, 256>>>((const float*)xb, ln2_s, ln2_b, (__half*)yb);

    // 6. MLP up + bias + gelu -> fp16 h  (N=2048, K=512)
    mma_gemm<1,1,0,1><<<GRID_P, 128, GEMM_SMEM>>>((__half*)yb, (__half*)w1p,
        b1, nullptr, nullptr, (__half*)hb, TOK, MLPD, DMODEL);

    // 7. MLP down + bias + residual -> out  (N=512, K=2048)
    mma_gemm<1,0,1,0><<<GRID_P, 128, GEMM_SMEM>>>((__half*)hb, (__half*)w2p,
        b2, (const float*)xb, out, nullptr, TOK, DMODEL, MLPD);
}